// round 1
// baseline (speedup 1.0000x reference)
#include <cuda_runtime.h>
#include <cuda_bf16.h>

// VEGAS adaptive-map transform.
// Inputs (metadata order): y [B,D] f32, grid [D,ninc+1] f32, inc [D,ninc] f32, ninc i32 (unused; derived from sizes)
// Output: x [B,D] f32 followed by jac [B] f32 in one buffer.

// Fast path: D == 16. Each thread handles 4 consecutive dims (one float4) of one
// sample. Tables live in shared memory (gathers would otherwise generate ~1GB of
// L2 sector traffic). Jacobian: local product of 4 factors + 2 butterfly shuffles.
__global__ void __launch_bounds__(1024, 1) vegas_map_d16_kernel(
    const float* __restrict__ y,
    const float* __restrict__ grd,
    const float* __restrict__ inc,
    float* __restrict__ xout,
    float* __restrict__ jac,
    int B, int ninc, int n_grid, int n_inc, int kmax)
{
    extern __shared__ float s[];
    float* sg = s;              // grid: D*(ninc+1)
    float* si = s + n_grid;     // inc:  D*ninc

    for (int i = threadIdx.x; i < n_grid; i += blockDim.x) sg[i] = grd[i];
    for (int i = threadIdx.x; i < n_inc;  i += blockDim.x) si[i] = inc[i];
    __syncthreads();

    const float nincf   = (float)ninc;
    const int   G       = B * 4;                      // number of float4 groups (D=16)
    const int   stride  = gridDim.x * blockDim.x;
    const int   lane    = threadIdx.x & 31;
    int g = blockIdx.x * blockDim.x + threadIdx.x;

    for (int k = 0; k < kmax; ++k, g += stride) {
        const bool ok   = g < G;
        const int  b    = g >> 2;                     // sample index
        const int  dbase = (g & 3) * 4;               // first dim this thread handles

        float4 y4 = make_float4(0.f, 0.f, 0.f, 0.f);
        if (ok) y4 = reinterpret_cast<const float4*>(y)[g];

        float yv[4] = {y4.x, y4.y, y4.z, y4.w};
        float xs[4];
        float p = 1.0f;

        #pragma unroll
        for (int j = 0; j < 4; ++j) {
            const int d = dbase + j;
            float t  = yv[j] * nincf;
            int   iy = (int)t;                        // y >= 0 -> trunc == floor
            if (iy > ninc) iy = ninc;                 // safety clamp
            const bool valid = iy < ninc;
            const float dy   = t - (float)iy;
            const int iyi    = valid ? iy : (ninc - 1);

            const float gv = sg[d * (ninc + 1) + iy]; // grid[d, iy] (iy<=ninc)
            const float hv = si[d * ninc + iyi];      // inc[d, iy] (clamped)

            xs[j] = valid ? fmaf(hv, dy, gv) : gv;    // out-of-range -> right edge
            p *= hv * nincf;                          // jacobian factor (edge case folds in)
        }

        if (ok) reinterpret_cast<float4*>(xout)[g] =
                    make_float4(xs[0], xs[1], xs[2], xs[3]);

        // product across the 4 lanes covering this sample (lanes aligned to 4)
        p *= __shfl_xor_sync(0xffffffffu, p, 1);
        p *= __shfl_xor_sync(0xffffffffu, p, 2);
        if (ok && (lane & 3) == 0) jac[b] = p;
    }
}

// Generic fallback (any D): one thread per sample, tables from global memory.
__global__ void vegas_map_generic_kernel(
    const float* __restrict__ y,
    const float* __restrict__ grd,
    const float* __restrict__ inc,
    float* __restrict__ xout,
    float* __restrict__ jac,
    int B, int D, int ninc)
{
    int b = blockIdx.x * blockDim.x + threadIdx.x;
    if (b >= B) return;
    const float nincf = (float)ninc;
    float p = 1.0f;
    for (int d = 0; d < D; ++d) {
        float t  = y[(size_t)b * D + d] * nincf;
        int   iy = (int)t;
        if (iy > ninc) iy = ninc;
        const bool valid = iy < ninc;
        const float dy   = t - (float)iy;
        const int iyi    = valid ? iy : (ninc - 1);
        const float gv = grd[d * (ninc + 1) + iy];
        const float hv = inc[d * ninc + iyi];
        xout[(size_t)b * D + d] = valid ? fmaf(hv, dy, gv) : gv;
        p *= hv * nincf;
    }
    jac[b] = p;
}

extern "C" void kernel_launch(void* const* d_in, const int* in_sizes, int n_in,
                              void* d_out, int out_size)
{
    const float* y   = (const float*)d_in[0];
    const float* grd = (const float*)d_in[1];
    const float* inc = (const float*)d_in[2];

    const int n_y = in_sizes[0];
    const int n_g = in_sizes[1];
    const int n_i = in_sizes[2];

    const int D    = n_g - n_i;          // D*(ninc+1) - D*ninc
    const int ninc = n_i / D;
    const int B    = n_y / D;

    float* x   = (float*)d_out;
    float* jac = x + (size_t)n_y;        // jac follows x

    const size_t smem = (size_t)(n_g + n_i) * sizeof(float);

    if (D == 16 && smem <= 200 * 1024) {
        cudaFuncSetAttribute(vegas_map_d16_kernel,
                             cudaFuncAttributeMaxDynamicSharedMemorySize,
                             (int)smem);
        int dev = 0;
        cudaGetDevice(&dev);
        int sms = 148;
        cudaDeviceGetAttribute(&sms, cudaDevAttrMultiProcessorCount, dev);

        const int threads = 1024;
        const int nCTA    = sms * 2;     // ~1 CTA/SM resident (smem-limited), 2 waves
        const long long G      = (long long)B * 4;
        const long long totThr = (long long)nCTA * threads;
        const int kmax = (int)((G + totThr - 1) / totThr);

        vegas_map_d16_kernel<<<nCTA, threads, smem>>>(
            y, grd, inc, x, jac, B, ninc, n_g, n_i, kmax);
    } else {
        const int threads = 256;
        const int blocks  = (B + threads - 1) / threads;
        vegas_map_generic_kernel<<<blocks, threads>>>(
            y, grd, inc, x, jac, B, D, ninc);
    }
}

// round 2
// speedup vs baseline: 1.1420x; 1.1420x over previous
#include <cuda_runtime.h>
#include <cuda_bf16.h>

// VEGAS adaptive-map transform.
// Inputs (metadata order): y [B,16] f32, grid [16,ninc+1] f32, inc [16,ninc] f32, ninc i32
// Output: x [B,16] f32 followed by jac [B] f32 in one buffer.
//
// Thread-per-sample design: each thread maps all 16 dims of one sample.
//  - 4 independent LDG.128 for y (MLP=4), 4 STG.128 for x, 1 coalesced STG.32 for jac.
//  - Combined smem table float2{grid[i], inc[i]} -> one LDS.64 per dim.
//    tab[d][ninc] = {grid[d,ninc], inc[d,ninc-1]} so the y>=1 clamp path needs no
//    special table handling.
//  - Single wave: gridDim = #SMs, kfull full grid-stride iterations + one guarded tail.

__global__ void __launch_bounds__(1024, 1) vegas_map_d16_kernel(
    const float* __restrict__ y,
    const float* __restrict__ grd,
    const float* __restrict__ inc,
    float* __restrict__ xout,
    float* __restrict__ jac,
    int B, int ninc, int kfull)
{
    extern __shared__ float2 tab[];            // [16][ninc+1] interleaved {g, h}
    const int np1 = ninc + 1;

    // Build interleaved table (grid layout in gmem is [16][ninc+1] row-major,
    // so flat index i works directly for the g component).
    for (int i = threadIdx.x; i < 16 * np1; i += blockDim.x) {
        const int d = i / np1;
        const int j = i - d * np1;
        const float g = grd[i];
        const float h = inc[d * ninc + ((j < ninc) ? j : (ninc - 1))];
        tab[i] = make_float2(g, h);
    }
    __syncthreads();

    const float nincf  = (float)ninc;
    const float nincf4 = (nincf * nincf) * (nincf * nincf);
    const int   stride = gridDim.x * blockDim.x;
    int b = blockIdx.x * blockDim.x + threadIdx.x;

    const float4* __restrict__ y4 = reinterpret_cast<const float4*>(y);
    float4* __restrict__ x4 = reinterpret_cast<float4*>(xout);

    for (int k = 0; k <= kfull; ++k, b += stride) {
        if (k == kfull && b >= B) break;       // tail guard (only last iteration)

        const size_t base = (size_t)b * 4;
        // Issue all 4 sample loads up front (independent -> MLP=4).
        float4 ya = y4[base + 0];
        float4 yb = y4[base + 1];
        float4 yc = y4[base + 2];
        float4 yd = y4[base + 3];

        float p = 1.0f;

        // Process one float4 group (4 dims), returns x4 and multiplies group
        // jacobian factor into p.
        #define GROUP(Y4, Q)                                                     \
        {                                                                        \
            float yv[4] = {Y4.x, Y4.y, Y4.z, Y4.w};                              \
            float xs[4];                                                         \
            float ph = 1.0f;                                                     \
            _Pragma("unroll")                                                    \
            for (int j = 0; j < 4; ++j) {                                        \
                const int d = (Q) * 4 + j;                                       \
                float t  = yv[j] * nincf;                                        \
                int   iy = (int)t;                  /* y>=0: trunc == floor */   \
                if (iy > ninc) iy = ninc;           /* safety clamp */           \
                const bool  valid = iy < ninc;                                   \
                const float dy    = t - (float)iy;                               \
                const float2 gh   = tab[d * np1 + iy];                           \
                xs[j] = valid ? fmaf(gh.y, dy, gh.x) : gh.x;                     \
                ph *= gh.y;            /* at iy==ninc, gh.y == inc[ninc-1] */    \
            }                                                                    \
            p *= ph * nincf4;                                                    \
            x4[base + (Q)] = make_float4(xs[0], xs[1], xs[2], xs[3]);            \
        }

        GROUP(ya, 0)
        GROUP(yb, 1)
        GROUP(yc, 2)
        GROUP(yd, 3)
        #undef GROUP

        jac[b] = p;
    }
}

// Generic fallback (any D): one thread per sample, tables from global memory.
__global__ void vegas_map_generic_kernel(
    const float* __restrict__ y,
    const float* __restrict__ grd,
    const float* __restrict__ inc,
    float* __restrict__ xout,
    float* __restrict__ jac,
    int B, int D, int ninc)
{
    int b = blockIdx.x * blockDim.x + threadIdx.x;
    if (b >= B) return;
    const float nincf = (float)ninc;
    float p = 1.0f;
    for (int d = 0; d < D; ++d) {
        float t  = y[(size_t)b * D + d] * nincf;
        int   iy = (int)t;
        if (iy > ninc) iy = ninc;
        const bool valid = iy < ninc;
        const float dy   = t - (float)iy;
        const int iyi    = valid ? iy : (ninc - 1);
        const float gv = grd[d * (ninc + 1) + iy];
        const float hv = inc[d * ninc + iyi];
        xout[(size_t)b * D + d] = valid ? fmaf(hv, dy, gv) : gv;
        p *= hv * nincf;
    }
    jac[b] = p;
}

extern "C" void kernel_launch(void* const* d_in, const int* in_sizes, int n_in,
                              void* d_out, int out_size)
{
    const float* y   = (const float*)d_in[0];
    const float* grd = (const float*)d_in[1];
    const float* inc = (const float*)d_in[2];

    const int n_y = in_sizes[0];
    const int n_g = in_sizes[1];
    const int n_i = in_sizes[2];

    const int D    = n_g - n_i;          // D*(ninc+1) - D*ninc
    const int ninc = n_i / D;
    const int B    = n_y / D;

    float* x   = (float*)d_out;
    float* jac = x + (size_t)n_y;        // jac follows x

    const size_t smem = (size_t)(16 * (ninc + 1)) * sizeof(float2);

    if (D == 16 && smem <= 200 * 1024) {
        cudaFuncSetAttribute(vegas_map_d16_kernel,
                             cudaFuncAttributeMaxDynamicSharedMemorySize,
                             (int)smem);
        int dev = 0;
        cudaGetDevice(&dev);
        int sms = 148;
        cudaDeviceGetAttribute(&sms, cudaDevAttrMultiProcessorCount, dev);

        const int threads = 1024;
        const int nCTA    = sms;                       // exactly one wave (1 CTA/SM)
        const int totThr  = nCTA * threads;
        const int kfull   = B / totThr;                // full unguarded iterations

        vegas_map_d16_kernel<<<nCTA, threads, smem>>>(
            y, grd, inc, x, jac, B, ninc, kfull);
    } else {
        const int threads = 256;
        const int blocks  = (B + threads - 1) / threads;
        vegas_map_generic_kernel<<<blocks, threads>>>(
            y, grd, inc, x, jac, B, D, ninc);
    }
}

// round 3
// speedup vs baseline: 1.1513x; 1.0082x over previous
#include <cuda_runtime.h>
#include <cuda_bf16.h>

// VEGAS adaptive-map transform.
// Inputs: y [B,16] f32, grid [16,ninc+1] f32, inc [16,ninc] f32, ninc i32
// Output: x [B,16] f32 followed by jac [B] f32.
//
// Layout: one thread per float4-group g (sample b=g>>2, quarter q=g&3).
// Consecutive lanes -> consecutive 16B -> every LDG.128/STG.128 perfectly
// coalesced. Jacobian: per-quarter partial product + 2 butterfly shuffles
// within each 4-lane sample group.
// Tables: split float arrays sg (grid) / sh (inc, with sh[d][ninc]=inc[d][ninc-1])
// in shared memory; one address serves both LDS (constant offset).
// Pipeline: 4 groups/thread/iter, next iteration's y prefetched during compute.

__global__ void __launch_bounds__(512, 1) vegas_map_d16_kernel(
    const float4* __restrict__ y4,
    const float* __restrict__ grd,
    const float* __restrict__ inc,
    float4* __restrict__ x4,
    float* __restrict__ jac,
    int G,            // B*4 float4 groups
    int ninc, int kfull)
{
    extern __shared__ float s[];
    const int np1 = ninc + 1;
    const int tabN = 16 * np1;
    float* sg = s;            // grid table [16][np1]
    float* sh = s + tabN;     // inc table  [16][np1], slot ninc = inc[ninc-1]

    for (int i = threadIdx.x; i < tabN; i += blockDim.x) {
        const int d = i / np1;
        const int j = i - d * np1;
        sg[i] = grd[i];
        sh[i] = inc[d * ninc + ((j < ninc) ? j : (ninc - 1))];
    }
    __syncthreads();

    const float nincf  = (float)ninc;
    const float nincf4 = (nincf * nincf) * (nincf * nincf);
    const int   T      = gridDim.x * blockDim.x;   // threads total (mult of 4)
    const int   lane   = threadIdx.x & 31;
    const int   g0     = blockIdx.x * blockDim.x + threadIdx.x;

    // quarter (g&3) is invariant across iterations since strides are mult of 4
    const int dbase = (g0 & 3) * 4;
    const int row0  = dbase * np1;   // row offsets row0 + j*np1, j=0..3

    float4 cur[4], nxt[4];
    const float4 z4 = make_float4(0.f, 0.f, 0.f, 0.f);

    #pragma unroll
    for (int i = 0; i < 4; ++i) {
        const int g = g0 + i * T;
        cur[i] = (g < G) ? y4[g] : z4;
    }

    for (int k = 0; k <= kfull; ++k) {
        const int base = g0 + k * 4 * T;

        // prefetch next iteration's data (overlaps with compute below)
        if (k < kfull) {
            #pragma unroll
            for (int i = 0; i < 4; ++i) {
                const int g = base + 4 * T + i * T;
                nxt[i] = (g < G) ? y4[g] : z4;
            }
        }

        #pragma unroll
        for (int i = 0; i < 4; ++i) {
            const int  g  = base + i * T;
            const bool ok = g < G;
            const float4 yv = cur[i];
            float vin[4] = {yv.x, yv.y, yv.z, yv.w};
            float xs[4];
            float ph = 1.0f;

            #pragma unroll
            for (int j = 0; j < 4; ++j) {
                float t  = vin[j] * nincf;
                int   iy = (int)t;                 // y>=0: trunc == floor
                iy = min(iy, ninc);
                const float dy = t - (float)iy;    // == 0 at the clamp point
                const int   a  = row0 + j * np1 + iy;
                const float gv = sg[a];
                const float hv = sh[a];            // inc[ninc-1] at clamp slot
                xs[j] = fmaf(hv, dy, gv);          // clamp: dy=0 -> exact edge
                ph *= hv;
            }
            ph *= nincf4;

            if (ok) x4[g] = make_float4(xs[0], xs[1], xs[2], xs[3]);

            // combine jacobian across the 4 lanes of this sample
            ph *= __shfl_xor_sync(0xffffffffu, ph, 1);
            ph *= __shfl_xor_sync(0xffffffffu, ph, 2);
            if (ok && (lane & 3) == 0) jac[g >> 2] = ph;
        }

        #pragma unroll
        for (int i = 0; i < 4; ++i) cur[i] = nxt[i];
    }
}

// Generic fallback (any D): one thread per sample, tables from global memory.
__global__ void vegas_map_generic_kernel(
    const float* __restrict__ y,
    const float* __restrict__ grd,
    const float* __restrict__ inc,
    float* __restrict__ xout,
    float* __restrict__ jac,
    int B, int D, int ninc)
{
    int b = blockIdx.x * blockDim.x + threadIdx.x;
    if (b >= B) return;
    const float nincf = (float)ninc;
    float p = 1.0f;
    for (int d = 0; d < D; ++d) {
        float t  = y[(size_t)b * D + d] * nincf;
        int   iy = (int)t;
        if (iy > ninc) iy = ninc;
        const bool valid = iy < ninc;
        const float dy   = t - (float)iy;
        const int iyi    = valid ? iy : (ninc - 1);
        const float gv = grd[d * (ninc + 1) + iy];
        const float hv = inc[d * ninc + iyi];
        xout[(size_t)b * D + d] = valid ? fmaf(hv, dy, gv) : gv;
        p *= hv * nincf;
    }
    jac[b] = p;
}

extern "C" void kernel_launch(void* const* d_in, const int* in_sizes, int n_in,
                              void* d_out, int out_size)
{
    const float* y   = (const float*)d_in[0];
    const float* grd = (const float*)d_in[1];
    const float* inc = (const float*)d_in[2];

    const int n_y = in_sizes[0];
    const int n_g = in_sizes[1];
    const int n_i = in_sizes[2];

    const int D    = n_g - n_i;          // D*(ninc+1) - D*ninc
    const int ninc = n_i / D;
    const int B    = n_y / D;

    float* x   = (float*)d_out;
    float* jac = x + (size_t)n_y;

    const size_t smem = (size_t)(2 * 16 * (ninc + 1)) * sizeof(float);

    if (D == 16 && smem <= 200 * 1024) {
        cudaFuncSetAttribute(vegas_map_d16_kernel,
                             cudaFuncAttributeMaxDynamicSharedMemorySize,
                             (int)smem);
        int dev = 0;
        cudaGetDevice(&dev);
        int sms = 148;
        cudaDeviceGetAttribute(&sms, cudaDevAttrMultiProcessorCount, dev);

        const int threads = 512;
        const int nCTA    = sms;                  // one wave, 1 CTA/SM
        const int T       = nCTA * threads;
        const int G       = B * 4;                // float4 groups
        const int perIter = 4 * T;
        const int kfull   = (G + perIter - 1) / perIter - 1;

        vegas_map_d16_kernel<<<nCTA, threads, smem>>>(
            (const float4*)y, grd, inc, (float4*)x, jac, G, ninc, kfull);
    } else {
        const int threads = 256;
        const int blocks  = (B + threads - 1) / threads;
        vegas_map_generic_kernel<<<blocks, threads>>>(
            y, grd, inc, x, jac, B, D, ninc);
    }
}

// round 4
// speedup vs baseline: 1.4058x; 1.2210x over previous
#include <cuda_runtime.h>
#include <cuda_bf16.h>

// VEGAS adaptive-map transform.
// Inputs: y [B,16] f32, grid [16,ninc+1] f32, inc [16,ninc] f32, ninc i32
// Output: x [B,16] f32 followed by jac [B] f32.
//
// Layout: one thread per float4-group g (sample b=g>>2, quarter q=g&3).
// Consecutive lanes -> consecutive 16B -> all LDG.128/STG.128 fully coalesced.
// Table: interleaved float2 {grid[i], inc[i]} in smem -> ONE LDS.64 per dim.
//   tab[d][ninc].y = inc[d][ninc-1]; at the clamp point dy==0, so
//   x = fma(h, dy, g) and p *= h need no selects at all.
// Occupancy: 1024 thr/CTA, 1 CTA/SM (128KB smem), <=64 regs -> 32 warps/SM.
// Pipeline: 2 groups/iter with depth-1 prefetch; unguarded main loop + tail.

__global__ void __launch_bounds__(1024, 1) vegas_map_d16_kernel(
    const float4* __restrict__ y4,
    const float* __restrict__ grd,
    const float* __restrict__ inc,
    float4* __restrict__ x4,
    float* __restrict__ jac,
    int G,            // B*4 float4 groups
    int ninc, int kfull)
{
    extern __shared__ float2 tab[];        // [16][ninc+1] interleaved {g, h}
    const int np1 = ninc + 1;

    for (int i = threadIdx.x; i < 16 * np1; i += blockDim.x) {
        const int d = i / np1;
        const int j = i - d * np1;
        tab[i] = make_float2(grd[i],
                             inc[d * ninc + ((j < ninc) ? j : (ninc - 1))]);
    }
    __syncthreads();

    const float nincf  = (float)ninc;
    const float nincf4 = (nincf * nincf) * (nincf * nincf);
    const int   T      = gridDim.x * blockDim.x;     // total threads (mult of 4)
    const int   lane   = threadIdx.x & 31;
    const int   g0     = blockIdx.x * blockDim.x + threadIdx.x;

    // quarter (g&3) invariant across iterations (strides are multiples of 4)
    const int row0 = ((g0 & 3) * 4) * np1;           // + j*np1 + iy per dim

    // per-group compute: consumes float4 yv for group index g (must be < G)
    #define PROCESS(YV, GIDX)                                                  \
    {                                                                          \
        float vin[4] = {(YV).x, (YV).y, (YV).z, (YV).w};                       \
        float xs[4];                                                           \
        float ph = 1.0f;                                                       \
        _Pragma("unroll")                                                      \
        for (int j = 0; j < 4; ++j) {                                          \
            float t  = vin[j] * nincf;                                         \
            int   iy = (int)t;                /* y>=0: trunc == floor */       \
            iy = min(iy, ninc);                                                \
            const float  dy = t - (float)iy;  /* == 0 at clamp point */        \
            const float2 gh = tab[row0 + j * np1 + iy];                        \
            xs[j] = fmaf(gh.y, dy, gh.x);                                      \
            ph *= gh.y;                                                        \
        }                                                                      \
        ph *= nincf4;                                                          \
        x4[(GIDX)] = make_float4(xs[0], xs[1], xs[2], xs[3]);                  \
        ph *= __shfl_xor_sync(0xffffffffu, ph, 1);                             \
        ph *= __shfl_xor_sync(0xffffffffu, ph, 2);                             \
        if ((lane & 3) == 0) jac[(GIDX) >> 2] = ph;                            \
    }

    float4 curA, curB, nxtA, nxtB;
    int g = g0;

    if (kfull > 0) {
        curA = y4[g];
        curB = y4[g + T];
        for (int k = 0; k < kfull; ++k) {
            const int gn = g + 2 * T;
            if (k + 1 < kfull) {               // depth-1 prefetch
                nxtA = y4[gn];
                nxtB = y4[gn + T];
            }
            PROCESS(curA, g)
            PROCESS(curB, g + T)
            curA = nxtA;
            curB = nxtB;
            g = gn;
        }
    }

    // guarded tail (< 2T groups remain)
    if (g < G)     { float4 yv = y4[g];     PROCESS(yv, g)     }
    if (g + T < G) { float4 yv = y4[g + T]; PROCESS(yv, g + T) }

    #undef PROCESS
}

// Generic fallback (any D): one thread per sample, tables from global memory.
__global__ void vegas_map_generic_kernel(
    const float* __restrict__ y,
    const float* __restrict__ grd,
    const float* __restrict__ inc,
    float* __restrict__ xout,
    float* __restrict__ jac,
    int B, int D, int ninc)
{
    int b = blockIdx.x * blockDim.x + threadIdx.x;
    if (b >= B) return;
    const float nincf = (float)ninc;
    float p = 1.0f;
    for (int d = 0; d < D; ++d) {
        float t  = y[(size_t)b * D + d] * nincf;
        int   iy = (int)t;
        if (iy > ninc) iy = ninc;
        const bool valid = iy < ninc;
        const float dy   = t - (float)iy;
        const int iyi    = valid ? iy : (ninc - 1);
        const float gv = grd[d * (ninc + 1) + iy];
        const float hv = inc[d * ninc + iyi];
        xout[(size_t)b * D + d] = valid ? fmaf(hv, dy, gv) : gv;
        p *= hv * nincf;
    }
    jac[b] = p;
}

extern "C" void kernel_launch(void* const* d_in, const int* in_sizes, int n_in,
                              void* d_out, int out_size)
{
    const float* y   = (const float*)d_in[0];
    const float* grd = (const float*)d_in[1];
    const float* inc = (const float*)d_in[2];

    const int n_y = in_sizes[0];
    const int n_g = in_sizes[1];
    const int n_i = in_sizes[2];

    const int D    = n_g - n_i;          // D*(ninc+1) - D*ninc
    const int ninc = n_i / D;
    const int B    = n_y / D;

    float* x   = (float*)d_out;
    float* jac = x + (size_t)n_y;

    const size_t smem = (size_t)(16 * (ninc + 1)) * sizeof(float2);

    if (D == 16 && smem <= 200 * 1024) {
        cudaFuncSetAttribute(vegas_map_d16_kernel,
                             cudaFuncAttributeMaxDynamicSharedMemorySize,
                             (int)smem);
        int dev = 0;
        cudaGetDevice(&dev);
        int sms = 148;
        cudaDeviceGetAttribute(&sms, cudaDevAttrMultiProcessorCount, dev);

        const int threads = 1024;
        const int nCTA    = sms;                 // one wave, 1 CTA/SM
        const int T       = nCTA * threads;
        const int G       = B * 4;               // float4 groups
        const int kfull   = G / (2 * T);         // unguarded iterations

        vegas_map_d16_kernel<<<nCTA, threads, smem>>>(
            (const float4*)y, grd, inc, (float4*)x, jac, G, ninc, kfull);
    } else {
        const int threads = 256;
        const int blocks  = (B + threads - 1) / threads;
        vegas_map_generic_kernel<<<blocks, threads>>>(
            y, grd, inc, x, jac, B, D, ninc);
    }
}